// round 2
// baseline (speedup 1.0000x reference)
#include <cuda_runtime.h>
#include <math.h>

#define BB   2
#define SS   2048
#define DMM  4096
#define HH   32
#define HKVV 8
#define DD   128
#define NTOK (BB*SS)      // 4096
#define QDIM (HH*DD)      // 4096
#define KVDIM (HKVV*DD)   // 1024

// Scratch (allocation-free rule: __device__ globals)
__device__ float g_Q[(size_t)NTOK*QDIM];
__device__ float g_K[(size_t)NTOK*KVDIM];
__device__ float g_V[(size_t)NTOK*KVDIM];
__device__ float g_attn[(size_t)NTOK*QDIM];
__device__ float g_cos[(size_t)NTOK*(DD/2)];
__device__ float g_sin[(size_t)NTOK*(DD/2)];

// ---------------------------------------------------------------------------
// RoPE table: cos/sin per (token, freq). inv_freq in double (rounded to f32),
// angle = f32(pos) * f32(inv_freq) with fp32 rounding to match the reference,
// then trig in double of that fp32 angle.
// ---------------------------------------------------------------------------
__global__ void rope_table_kernel(const int* __restrict__ pos)
{
    int idx = blockIdx.x * blockDim.x + threadIdx.x;
    if (idx >= NTOK * 64) return;
    int t = idx >> 6;
    int i = idx & 63;
    double invf_d = exp(-((double)i / 64.0) * log(10000.0));
    float invf = (float)invf_d;
    float ang = (float)pos[t] * invf;       // fp32 multiply, like the reference
    double a = (double)ang;
    g_cos[idx] = (float)cos(a);
    g_sin[idx] = (float)sin(a);
}

// ---------------------------------------------------------------------------
// GEMM: C[n][o] = sum_k X[n][k] * W[o][k]   (X: NTOK x DMM, W: OUTD x DMM)
// BM=BN=128, BK=16, 256 threads, 8x8 register tile, double-buffered smem.
// ---------------------------------------------------------------------------
template<int OUTD>
__global__ __launch_bounds__(256) void gemm_kernel(
    const float* __restrict__ X, const float* __restrict__ W, float* __restrict__ C)
{
    __shared__ __align__(16) float Xs[2][16][132];
    __shared__ __align__(16) float Ws[2][16][132];

    const int tid  = threadIdx.x;
    const int bm   = blockIdx.y * 128;
    const int bn   = blockIdx.x * 128;
    const int ty   = tid >> 4;
    const int tx   = tid & 15;
    const int lrow = tid >> 2;
    const int lcol = tid & 3;

    const float* Xp = X + (size_t)(bm + lrow) * DMM + lcol * 4;
    const float* Wp = W + (size_t)(bn + lrow) * DMM + lcol * 4;

    float acc[8][8];
#pragma unroll
    for (int i = 0; i < 8; i++)
#pragma unroll
        for (int j = 0; j < 8; j++) acc[i][j] = 0.f;

    // preload tile 0
    {
        float4 x0 = *(const float4*)Xp;
        float4 x1 = *(const float4*)(Xp + (size_t)64 * DMM);
        float4 w0 = *(const float4*)Wp;
        float4 w1 = *(const float4*)(Wp + (size_t)64 * DMM);
        Xs[0][lcol*4+0][lrow] = x0.x; Xs[0][lcol*4+1][lrow] = x0.y;
        Xs[0][lcol*4+2][lrow] = x0.z; Xs[0][lcol*4+3][lrow] = x0.w;
        Xs[0][lcol*4+0][lrow+64] = x1.x; Xs[0][lcol*4+1][lrow+64] = x1.y;
        Xs[0][lcol*4+2][lrow+64] = x1.z; Xs[0][lcol*4+3][lrow+64] = x1.w;
        Ws[0][lcol*4+0][lrow] = w0.x; Ws[0][lcol*4+1][lrow] = w0.y;
        Ws[0][lcol*4+2][lrow] = w0.z; Ws[0][lcol*4+3][lrow] = w0.w;
        Ws[0][lcol*4+0][lrow+64] = w1.x; Ws[0][lcol*4+1][lrow+64] = w1.y;
        Ws[0][lcol*4+2][lrow+64] = w1.z; Ws[0][lcol*4+3][lrow+64] = w1.w;
    }
    __syncthreads();

    int buf = 0;
    const int KT = DMM / 16;
    for (int kt = 0; kt < KT; kt++) {
        float4 x0, x1, w0, w1;
        const bool pf = (kt + 1 < KT);
        if (pf) {
            const float* xp = Xp + (kt + 1) * 16;
            x0 = *(const float4*)xp;
            x1 = *(const float4*)(xp + (size_t)64 * DMM);
            const float* wp = Wp + (kt + 1) * 16;
            w0 = *(const float4*)wp;
            w1 = *(const float4*)(wp + (size_t)64 * DMM);
        }
#pragma unroll
        for (int kk = 0; kk < 16; kk++) {
            float a[8], b[8];
            *(float4*)&a[0] = *(const float4*)&Xs[buf][kk][ty*8];
            *(float4*)&a[4] = *(const float4*)&Xs[buf][kk][ty*8+4];
            *(float4*)&b[0] = *(const float4*)&Ws[buf][kk][tx*8];
            *(float4*)&b[4] = *(const float4*)&Ws[buf][kk][tx*8+4];
#pragma unroll
            for (int i = 0; i < 8; i++)
#pragma unroll
                for (int j = 0; j < 8; j++)
                    acc[i][j] += a[i] * b[j];
        }
        if (pf) {
            const int nb = buf ^ 1;
            Xs[nb][lcol*4+0][lrow] = x0.x; Xs[nb][lcol*4+1][lrow] = x0.y;
            Xs[nb][lcol*4+2][lrow] = x0.z; Xs[nb][lcol*4+3][lrow] = x0.w;
            Xs[nb][lcol*4+0][lrow+64] = x1.x; Xs[nb][lcol*4+1][lrow+64] = x1.y;
            Xs[nb][lcol*4+2][lrow+64] = x1.z; Xs[nb][lcol*4+3][lrow+64] = x1.w;
            Ws[nb][lcol*4+0][lrow] = w0.x; Ws[nb][lcol*4+1][lrow] = w0.y;
            Ws[nb][lcol*4+2][lrow] = w0.z; Ws[nb][lcol*4+3][lrow] = w0.w;
            Ws[nb][lcol*4+0][lrow+64] = w1.x; Ws[nb][lcol*4+1][lrow+64] = w1.y;
            Ws[nb][lcol*4+2][lrow+64] = w1.z; Ws[nb][lcol*4+3][lrow+64] = w1.w;
        }
        __syncthreads();
        buf ^= 1;
    }

#pragma unroll
    for (int i = 0; i < 8; i++) {
        float* cp = C + (size_t)(bm + ty*8 + i) * OUTD + bn + tx*8;
        float4 v0 = make_float4(acc[i][0], acc[i][1], acc[i][2], acc[i][3]);
        float4 v1 = make_float4(acc[i][4], acc[i][5], acc[i][6], acc[i][7]);
        *(float4*)cp = v0;
        *(float4*)(cp + 4) = v1;
    }
}

// ---------------------------------------------------------------------------
// RoPE apply (in place, Q and K). One warp per (token, head-slot).
// ---------------------------------------------------------------------------
__global__ void rope_apply_kernel(float* __restrict__ Q, float* __restrict__ K)
{
    int t    = blockIdx.x;
    int slot = blockIdx.y * 4 + (threadIdx.x >> 5);
    int lane = threadIdx.x & 31;
    float* base = (slot < HH)
        ? (Q + (size_t)t * QDIM + slot * DD)
        : (K + (size_t)t * KVDIM + (slot - HH) * DD);
#pragma unroll
    for (int rep = 0; rep < 2; rep++) {
        int i = lane + rep * 32;
        float c = g_cos[(size_t)t * 64 + i];
        float s = g_sin[(size_t)t * 64 + i];
        float x1 = base[i];
        float x2 = base[i + 64];
        base[i]      = x1 * c - x2 * s;
        base[i + 64] = x2 * c + x1 * s;
    }
}

// ---------------------------------------------------------------------------
// Causal GQA flash attention, fp32.
// BLOCK_M=64 q-rows per CTA, BLOCK_N=32 k-rows per tile, 128 threads.
// Thread t: q-row r=t>>1, dim-half h2=t&1 (64 dims each in registers).
// ---------------------------------------------------------------------------
__global__ __launch_bounds__(128) void flash_kernel(
    const float* __restrict__ Q, const float* __restrict__ K,
    const float* __restrict__ V, float* __restrict__ O)
{
    __shared__ __align__(16) float Ks[32 * 128];
    __shared__ __align__(16) float Vs[32 * 128];
    __shared__ float Sx[64 * 33];

    const int mt = blockIdx.x;
    const int h  = blockIdx.y;
    const int b  = blockIdx.z;
    const int kvh = h >> 2;              // H/HKV = 4
    const int t  = threadIdx.x;
    const int r  = t >> 1;
    const int h2 = t & 1;
    const int qi = mt * 64 + r;
    const float scale = 0.08838834764831843f;   // 1/sqrt(128)

    float q[64], acc[64];
    const float* Qg = Q + (size_t)(b * SS + qi) * QDIM + h * DD + h2 * 64;
#pragma unroll
    for (int dd = 0; dd < 16; dd++) {
        float4 v = *(const float4*)(Qg + dd * 4);
        q[dd*4+0] = v.x * scale; q[dd*4+1] = v.y * scale;
        q[dd*4+2] = v.z * scale; q[dd*4+3] = v.w * scale;
        acc[dd*4+0] = 0.f; acc[dd*4+1] = 0.f; acc[dd*4+2] = 0.f; acc[dd*4+3] = 0.f;
    }
    float m_i = -1e30f, l_i = 0.f;

    const float* Kg = K + (size_t)(b * SS) * KVDIM + kvh * DD;
    const float* Vg = V + (size_t)(b * SS) * KVDIM + kvh * DD;

    const int ntiles = 2 * (mt + 1);
    for (int nt = 0; nt < ntiles; nt++) {
        __syncthreads();
        // load K/V tiles: 32 rows x 128 cols, 8 float4 per thread each
#pragma unroll
        for (int i = 0; i < 8; i++) {
            int f = t + i * 128;
            int row = f >> 5;
            int cs  = f & 31;
            const float* sk = Kg + (size_t)(nt * 32 + row) * KVDIM + cs * 4;
            const float* sv = Vg + (size_t)(nt * 32 + row) * KVDIM + cs * 4;
            *(float4*)&Ks[row * 128 + cs * 4] = *(const float4*)sk;
            *(float4*)&Vs[row * 128 + cs * 4] = *(const float4*)sv;
        }
        __syncthreads();

        // scores: each pair-thread computes partial over its 64 dims, combine via shfl
        for (int j = 0; j < 32; j++) {
            const float* kr = &Ks[j * 128 + h2 * 64];
            float p = 0.f;
#pragma unroll
            for (int dd = 0; dd < 16; dd++) {
                float4 kv = *(const float4*)(kr + dd * 4);
                p += q[dd*4+0]*kv.x + q[dd*4+1]*kv.y + q[dd*4+2]*kv.z + q[dd*4+3]*kv.w;
            }
            p += __shfl_xor_sync(0xffffffffu, p, 1);
            if (nt * 32 + j > qi) p = -1e30f;
            if (h2 == 0) Sx[r * 33 + j] = p;
        }
        __syncthreads();

        // online softmax; each pair-thread owns half the 32 columns
        const int j0 = h2 * 16;
        float mloc = -1e30f;
        for (int j = j0; j < j0 + 16; j++) mloc = fmaxf(mloc, Sx[r * 33 + j]);
        mloc = fmaxf(mloc, __shfl_xor_sync(0xffffffffu, mloc, 1));
        float mnew  = fmaxf(m_i, mloc);
        float alpha = __expf(m_i - mnew);
        float lloc = 0.f;
        for (int j = j0; j < j0 + 16; j++) {
            float e = __expf(Sx[r * 33 + j] - mnew);
            Sx[r * 33 + j] = e;
            lloc += e;
        }
        lloc += __shfl_xor_sync(0xffffffffu, lloc, 1);
        l_i = l_i * alpha + lloc;
        m_i = mnew;
#pragma unroll
        for (int d2 = 0; d2 < 64; d2++) acc[d2] *= alpha;
        __syncwarp();

        // P @ V
        for (int j = 0; j < 32; j++) {
            float pj = Sx[r * 33 + j];
            const float* vr = &Vs[j * 128 + h2 * 64];
#pragma unroll
            for (int dd = 0; dd < 16; dd++) {
                float4 vv = *(const float4*)(vr + dd * 4);
                acc[dd*4+0] += pj * vv.x; acc[dd*4+1] += pj * vv.y;
                acc[dd*4+2] += pj * vv.z; acc[dd*4+3] += pj * vv.w;
            }
        }
    }

    float inv = 1.f / l_i;
    float* Og = O + (size_t)(b * SS + qi) * QDIM + h * DD + h2 * 64;
#pragma unroll
    for (int dd = 0; dd < 16; dd++) {
        float4 v = make_float4(acc[dd*4+0]*inv, acc[dd*4+1]*inv,
                               acc[dd*4+2]*inv, acc[dd*4+3]*inv);
        *(float4*)(Og + dd * 4) = v;
    }
}

// ---------------------------------------------------------------------------
extern "C" void kernel_launch(void* const* d_in, const int* in_sizes, int n_in,
                              void* d_out, int out_size)
{
    const float* hs  = (const float*)d_in[0];
    const int*   pos = (const int*)d_in[1];
    const float* Wq  = (const float*)d_in[2];
    const float* Wk  = (const float*)d_in[3];
    const float* Wv  = (const float*)d_in[4];
    const float* Wo  = (const float*)d_in[5];
    float* out = (float*)d_out;

    float *Qb, *Kb, *Vb, *Ab;
    cudaGetSymbolAddress((void**)&Qb, g_Q);
    cudaGetSymbolAddress((void**)&Kb, g_K);
    cudaGetSymbolAddress((void**)&Vb, g_V);
    cudaGetSymbolAddress((void**)&Ab, g_attn);

    rope_table_kernel<<<(NTOK * 64) / 256, 256>>>(pos);

    gemm_kernel<QDIM> <<<dim3(QDIM / 128, NTOK / 128), 256>>>(hs, Wq, Qb);
    gemm_kernel<KVDIM><<<dim3(KVDIM / 128, NTOK / 128), 256>>>(hs, Wk, Kb);
    gemm_kernel<KVDIM><<<dim3(KVDIM / 128, NTOK / 128), 256>>>(hs, Wv, Vb);

    rope_apply_kernel<<<dim3(NTOK, (HH + HKVV) / 4), 128>>>(Qb, Kb);

    flash_kernel<<<dim3(SS / 64, HH, BB), 128>>>(Qb, Kb, Vb, Ab);

    gemm_kernel<QDIM><<<dim3(QDIM / 128, NTOK / 128), 256>>>(Ab, Wo, out);
}

// round 4
// speedup vs baseline: 1.0085x; 1.0085x over previous
#include <cuda_runtime.h>
#include <cuda_bf16.h>
#include <math.h>
#include <cstdint>

#define BB   2
#define SS   2048
#define DMM  4096
#define HH   32
#define HKVV 8
#define DD   128
#define NTOK (BB*SS)      // 4096
#define QDIM (HH*DD)      // 4096
#define KVDIM (HKVV*DD)   // 1024

// ---------------- scratch (__device__ globals; allocation-free rule) -------
__device__ __align__(256) float g_Q[(size_t)NTOK*QDIM];
__device__ __align__(256) float g_K[(size_t)NTOK*KVDIM];
__device__ __align__(256) float g_V[(size_t)NTOK*KVDIM];
__device__ __align__(256) float g_attn[(size_t)NTOK*QDIM];
__device__ float g_cos[(size_t)NTOK*64];
__device__ float g_sin[(size_t)NTOK*64];
__device__ __align__(256) __nv_bfloat16 g_Ahi[(size_t)NTOK*DMM];
__device__ __align__(256) __nv_bfloat16 g_Alo[(size_t)NTOK*DMM];
__device__ __align__(256) __nv_bfloat16 g_Bhi[(size_t)QDIM*DMM];
__device__ __align__(256) __nv_bfloat16 g_Blo[(size_t)QDIM*DMM];

// ---------------------------- PTX helpers (baseline ISA only) --------------
__device__ __forceinline__ uint32_t smem_u32(const void* p) {
    uint32_t a;
    asm("{ .reg .u64 t; cvta.to.shared.u64 t, %1; cvt.u32.u64 %0, t; }"
        : "=r"(a) : "l"(p));
    return a;
}
#define CP_ASYNC16(saddr, gptr) \
    asm volatile("cp.async.cg.shared.global [%0], [%1], 16;\n" \
        :: "r"(saddr), "l"(gptr) : "memory")
#define CP_COMMIT() asm volatile("cp.async.commit_group;\n" ::: "memory")
#define CP_WAIT0()  asm volatile("cp.async.wait_group 0;\n" ::: "memory")

__device__ __forceinline__ void ldsm_x4(uint32_t* r, uint32_t addr) {
    asm volatile("ldmatrix.sync.aligned.m8n8.x4.shared.b16 {%0,%1,%2,%3}, [%4];\n"
        : "=r"(r[0]), "=r"(r[1]), "=r"(r[2]), "=r"(r[3]) : "r"(addr));
}
__device__ __forceinline__ void mma_bf16(float* d, const uint32_t* a,
                                         uint32_t b0, uint32_t b1) {
    asm volatile(
        "mma.sync.aligned.m16n8k16.row.col.f32.bf16.bf16.f32 "
        "{%0,%1,%2,%3}, {%4,%5,%6,%7}, {%8,%9}, {%0,%1,%2,%3};\n"
        : "+f"(d[0]), "+f"(d[1]), "+f"(d[2]), "+f"(d[3])
        : "r"(a[0]), "r"(a[1]), "r"(a[2]), "r"(a[3]), "r"(b0), "r"(b1));
}

// ---------------------------------------------------------------------------
// fp32 -> (bf16 hi, bf16 lo) split
// ---------------------------------------------------------------------------
__global__ void convert_hilo(const float* __restrict__ src,
                             __nv_bfloat16* __restrict__ hi,
                             __nv_bfloat16* __restrict__ lo, int n4)
{
    int i = blockIdx.x * blockDim.x + threadIdx.x;
    if (i >= n4) return;
    float4 x = ((const float4*)src)[i];
    __nv_bfloat16 h0 = __float2bfloat16(x.x);
    __nv_bfloat16 h1 = __float2bfloat16(x.y);
    __nv_bfloat16 h2 = __float2bfloat16(x.z);
    __nv_bfloat16 h3 = __float2bfloat16(x.w);
    __nv_bfloat16 l0 = __float2bfloat16(x.x - __bfloat162float(h0));
    __nv_bfloat16 l1 = __float2bfloat16(x.y - __bfloat162float(h1));
    __nv_bfloat16 l2 = __float2bfloat16(x.z - __bfloat162float(h2));
    __nv_bfloat16 l3 = __float2bfloat16(x.w - __bfloat162float(h3));
    __nv_bfloat162 hh0; hh0.x = h0; hh0.y = h1;
    __nv_bfloat162 hh1; hh1.x = h2; hh1.y = h3;
    __nv_bfloat162 ll0; ll0.x = l0; ll0.y = l1;
    __nv_bfloat162 ll1; ll1.x = l2; ll1.y = l3;
    ((__nv_bfloat162*)hi)[2*i]   = hh0;
    ((__nv_bfloat162*)hi)[2*i+1] = hh1;
    ((__nv_bfloat162*)lo)[2*i]   = ll0;
    ((__nv_bfloat162*)lo)[2*i+1] = ll1;
}

// ---------------------------------------------------------------------------
// HMMA compensated-bf16 GEMM: C[m][n] = sum_k A[m][k]*B[n][k], K=DMM.
// BM=BN=128, BK=32, 256 thr (8 warps = 2x4), warp tile 64x32.
// smem rows padded to 40 bf16 (80B): stride 80 mod 128 covers all eight 16B
// phases -> conflict-free ldmatrix, no swizzle.
// Buffer: Ahi[0,10240) Alo[10240,20480) Bhi[20480,30720) Blo[30720,40960)
// ---------------------------------------------------------------------------
#define RSB   80      // row stride bytes
#define AHI_O 0
#define ALO_O 10240
#define BHI_O 20480
#define BLO_O 30720
#define BUF_B 40960

__device__ __forceinline__ void issue_loads(uint32_t sbuf,
    const __nv_bfloat16* __restrict__ Ahi, const __nv_bfloat16* __restrict__ Alo,
    const __nv_bfloat16* __restrict__ Bhi, const __nv_bfloat16* __restrict__ Blo,
    int bm, int bn, int kc, int tid)
{
    const size_t koff = (size_t)kc * 32;
#pragma unroll
    for (int i = 0; i < 2; i++) {
        int u = tid + i * 256;          // 512 units of 16B per matrix
        int row = u >> 2, c = u & 3;
        uint32_t so = row * RSB + c * 16;
        size_t ga = (size_t)(bm + row) * DMM + koff + c * 8;
        size_t gb = (size_t)(bn + row) * DMM + koff + c * 8;
        CP_ASYNC16(sbuf + AHI_O + so, Ahi + ga);
        CP_ASYNC16(sbuf + ALO_O + so, Alo + ga);
        CP_ASYNC16(sbuf + BHI_O + so, Bhi + gb);
        CP_ASYNC16(sbuf + BLO_O + so, Blo + gb);
    }
    CP_COMMIT();
}

template<int OUTD>
__global__ __launch_bounds__(256) void hmma_gemm(
    const __nv_bfloat16* __restrict__ Ahi, const __nv_bfloat16* __restrict__ Alo,
    const __nv_bfloat16* __restrict__ Bhi, const __nv_bfloat16* __restrict__ Blo,
    float* __restrict__ C)
{
    extern __shared__ __align__(128) char smc[];
    const int tid  = threadIdx.x;
    const int wid  = tid >> 5;
    const int lane = tid & 31;
    const int warp_m = wid >> 2;        // 0..1
    const int warp_n = wid & 3;         // 0..3
    const int bm = blockIdx.y * 128;
    const int bn = blockIdx.x * 128;

    const uint32_t sm0 = smem_u32(smc);

    float acc[4][4][4];
#pragma unroll
    for (int fm = 0; fm < 4; fm++)
#pragma unroll
        for (int fn = 0; fn < 4; fn++)
#pragma unroll
            for (int e = 0; e < 4; e++) acc[fm][fn][e] = 0.f;

    // per-lane ldmatrix address components (bytes)
    const uint32_t aoff = (uint32_t)((lane & 15) * RSB + (lane >> 4) * 16);
    const uint32_t boff = (uint32_t)(((lane & 7) + ((lane & 16) >> 1)) * RSB
                                     + ((lane & 8) ? 16 : 0));

    issue_loads(sm0, Ahi, Alo, Bhi, Blo, bm, bn, 0, tid);
    CP_WAIT0();
    __syncthreads();

    const int KT = DMM / 32;
    for (int kc = 0; kc < KT; kc++) {
        if (kc + 1 < KT)
            issue_loads(sm0 + ((kc + 1) & 1) * BUF_B, Ahi, Alo, Bhi, Blo, bm, bn, kc + 1, tid);

        const uint32_t sb = sm0 + (kc & 1) * BUF_B;
        const uint32_t abase = sb + (uint32_t)(warp_m * 64) * RSB;
        const uint32_t bbase = sb + (uint32_t)(warp_n * 32) * RSB;

#pragma unroll
        for (int ks = 0; ks < 2; ks++) {
            const uint32_t k0b = ks * 32;      // 16 bf16 = 32 bytes
            uint32_t Ah[4][4], Al[4][4], Bh[2][4], Bl[2][4];
#pragma unroll
            for (int fm = 0; fm < 4; fm++) {
                uint32_t ra = abase + (uint32_t)(fm * 16) * RSB + aoff + k0b;
                ldsm_x4(Ah[fm], ra + AHI_O);
                ldsm_x4(Al[fm], ra + ALO_O);
            }
#pragma unroll
            for (int g = 0; g < 2; g++) {
                uint32_t rb = bbase + (uint32_t)(g * 16) * RSB + boff + k0b;
                ldsm_x4(Bh[g], rb + BHI_O);
                ldsm_x4(Bl[g], rb + BLO_O);
            }
#pragma unroll
            for (int fm = 0; fm < 4; fm++)
#pragma unroll
                for (int fn = 0; fn < 4; fn++) {
                    const int g = fn >> 1, h = (fn & 1) * 2;
                    mma_bf16(acc[fm][fn], Ah[fm], Bh[g][h], Bh[g][h+1]);
                    mma_bf16(acc[fm][fn], Ah[fm], Bl[g][h], Bl[g][h+1]);
                    mma_bf16(acc[fm][fn], Al[fm], Bh[g][h], Bh[g][h+1]);
                }
        }
        CP_WAIT0();
        __syncthreads();
    }

    // epilogue: c0/c1 -> (r, c), (r, c+1); c2/c3 -> (r+8, ...)
    const int r0 = bm + warp_m * 64 + (lane >> 2);
    const int c0 = bn + warp_n * 32 + (lane & 3) * 2;
#pragma unroll
    for (int fm = 0; fm < 4; fm++)
#pragma unroll
        for (int fn = 0; fn < 4; fn++) {
            const int row = r0 + fm * 16;
            const int col = c0 + fn * 8;
            float2 v0 = make_float2(acc[fm][fn][0], acc[fm][fn][1]);
            float2 v1 = make_float2(acc[fm][fn][2], acc[fm][fn][3]);
            *(float2*)&C[(size_t)row * OUTD + col] = v0;
            *(float2*)&C[(size_t)(row + 8) * OUTD + col] = v1;
        }
}

// ---------------------------------------------------------------------------
// RoPE table (fp32 angle rounding matches the reference)
// ---------------------------------------------------------------------------
__global__ void rope_table_kernel(const int* __restrict__ pos)
{
    int idx = blockIdx.x * blockDim.x + threadIdx.x;
    if (idx >= NTOK * 64) return;
    int t = idx >> 6;
    int i = idx & 63;
    double invf_d = exp(-((double)i / 64.0) * log(10000.0));
    float invf = (float)invf_d;
    float ang = (float)pos[t] * invf;
    double a = (double)ang;
    g_cos[idx] = (float)cos(a);
    g_sin[idx] = (float)sin(a);
}

__global__ void rope_apply_kernel(float* __restrict__ Q, float* __restrict__ K)
{
    int t    = blockIdx.x;
    int slot = blockIdx.y * 4 + (threadIdx.x >> 5);
    int lane = threadIdx.x & 31;
    float* base = (slot < HH)
        ? (Q + (size_t)t * QDIM + slot * DD)
        : (K + (size_t)t * KVDIM + (slot - HH) * DD);
#pragma unroll
    for (int rep = 0; rep < 2; rep++) {
        int i = lane + rep * 32;
        float c = g_cos[(size_t)t * 64 + i];
        float s = g_sin[(size_t)t * 64 + i];
        float x1 = base[i];
        float x2 = base[i + 64];
        base[i]      = x1 * c - x2 * s;
        base[i + 64] = x2 * c + x1 * s;
    }
}

// ---------------------------------------------------------------------------
// Causal GQA flash attention (fp32 SIMT) — unchanged from R2 passing version
// ---------------------------------------------------------------------------
__global__ __launch_bounds__(128) void flash_kernel(
    const float* __restrict__ Q, const float* __restrict__ K,
    const float* __restrict__ V, float* __restrict__ O)
{
    __shared__ __align__(16) float Ks[32 * 128];
    __shared__ __align__(16) float Vs[32 * 128];
    __shared__ float Sx[64 * 33];

    const int mt = blockIdx.x;
    const int h  = blockIdx.y;
    const int b  = blockIdx.z;
    const int kvh = h >> 2;
    const int t  = threadIdx.x;
    const int r  = t >> 1;
    const int h2 = t & 1;
    const int qi = mt * 64 + r;
    const float scale = 0.08838834764831843f;

    float q[64], acc[64];
    const float* Qg = Q + (size_t)(b * SS + qi) * QDIM + h * DD + h2 * 64;
#pragma unroll
    for (int dd = 0; dd < 16; dd++) {
        float4 v = *(const float4*)(Qg + dd * 4);
        q[dd*4+0] = v.x * scale; q[dd*4+1] = v.y * scale;
        q[dd*4+2] = v.z * scale; q[dd*4+3] = v.w * scale;
        acc[dd*4+0] = 0.f; acc[dd*4+1] = 0.f; acc[dd*4+2] = 0.f; acc[dd*4+3] = 0.f;
    }
    float m_i = -1e30f, l_i = 0.f;

    const float* Kg = K + (size_t)(b * SS) * KVDIM + kvh * DD;
    const float* Vg = V + (size_t)(b * SS) * KVDIM + kvh * DD;

    const int ntiles = 2 * (mt + 1);
    for (int nt = 0; nt < ntiles; nt++) {
        __syncthreads();
#pragma unroll
        for (int i = 0; i < 8; i++) {
            int f = t + i * 128;
            int row = f >> 5;
            int cs  = f & 31;
            const float* sk = Kg + (size_t)(nt * 32 + row) * KVDIM + cs * 4;
            const float* sv = Vg + (size_t)(nt * 32 + row) * KVDIM + cs * 4;
            *(float4*)&Ks[row * 128 + cs * 4] = *(const float4*)sk;
            *(float4*)&Vs[row * 128 + cs * 4] = *(const float4*)sv;
        }
        __syncthreads();

        for (int j = 0; j < 32; j++) {
            const float* kr = &Ks[j * 128 + h2 * 64];
            float p = 0.f;
#pragma unroll
            for (int dd = 0; dd < 16; dd++) {
                float4 kv = *(const float4*)(kr + dd * 4);
                p += q[dd*4+0]*kv.x + q[dd*4+1]*kv.y + q[dd*4+2]*kv.z + q[dd*4+3]*kv.w;
            }
            p += __shfl_xor_sync(0xffffffffu, p, 1);
            if (nt * 32 + j > qi) p = -1e30f;
            if (h2 == 0) Sx[r * 33 + j] = p;
        }
        __syncthreads();

        const int j0 = h2 * 16;
        float mloc = -1e30f;
        for (int j = j0; j < j0 + 16; j++) mloc = fmaxf(mloc, Sx[r * 33 + j]);
        mloc = fmaxf(mloc, __shfl_xor_sync(0xffffffffu, mloc, 1));
        float mnew  = fmaxf(m_i, mloc);
        float alpha = __expf(m_i - mnew);
        float lloc = 0.f;
        for (int j = j0; j < j0 + 16; j++) {
            float e = __expf(Sx[r * 33 + j] - mnew);
            Sx[r * 33 + j] = e;
            lloc += e;
        }
        lloc += __shfl_xor_sync(0xffffffffu, lloc, 1);
        l_i = l_i * alpha + lloc;
        m_i = mnew;
#pragma unroll
        for (int d2 = 0; d2 < 64; d2++) acc[d2] *= alpha;
        __syncwarp();

        for (int j = 0; j < 32; j++) {
            float pj = Sx[r * 33 + j];
            const float* vr = &Vs[j * 128 + h2 * 64];
#pragma unroll
            for (int dd = 0; dd < 16; dd++) {
                float4 vv = *(const float4*)(vr + dd * 4);
                acc[dd*4+0] += pj * vv.x; acc[dd*4+1] += pj * vv.y;
                acc[dd*4+2] += pj * vv.z; acc[dd*4+3] += pj * vv.w;
            }
        }
    }

    float inv = 1.f / l_i;
    float* Og = O + (size_t)(b * SS + qi) * QDIM + h * DD + h2 * 64;
#pragma unroll
    for (int dd = 0; dd < 16; dd++) {
        float4 v = make_float4(acc[dd*4+0]*inv, acc[dd*4+1]*inv,
                               acc[dd*4+2]*inv, acc[dd*4+3]*inv);
        *(float4*)(Og + dd * 4) = v;
    }
}

// ---------------------------------------------------------------------------
extern "C" void kernel_launch(void* const* d_in, const int* in_sizes, int n_in,
                              void* d_out, int out_size)
{
    const float* hs  = (const float*)d_in[0];
    const int*   pos = (const int*)d_in[1];
    const float* Wq  = (const float*)d_in[2];
    const float* Wk  = (const float*)d_in[3];
    const float* Wv  = (const float*)d_in[4];
    const float* Wo  = (const float*)d_in[5];
    float* out = (float*)d_out;

    float *Qb, *Kb, *Vb, *Ab;
    __nv_bfloat16 *Ahi, *Alo, *Bhi, *Blo;
    cudaGetSymbolAddress((void**)&Qb, g_Q);
    cudaGetSymbolAddress((void**)&Kb, g_K);
    cudaGetSymbolAddress((void**)&Vb, g_V);
    cudaGetSymbolAddress((void**)&Ab, g_attn);
    cudaGetSymbolAddress((void**)&Ahi, g_Ahi);
    cudaGetSymbolAddress((void**)&Alo, g_Alo);
    cudaGetSymbolAddress((void**)&Bhi, g_Bhi);
    cudaGetSymbolAddress((void**)&Blo, g_Blo);

    cudaFuncSetAttribute(hmma_gemm<QDIM>,  cudaFuncAttributeMaxDynamicSharedMemorySize, 2*BUF_B);
    cudaFuncSetAttribute(hmma_gemm<KVDIM>, cudaFuncAttributeMaxDynamicSharedMemorySize, 2*BUF_B);

    const int nBig = NTOK * DMM / 4;
    const int nKV  = KVDIM * DMM / 4;

    rope_table_kernel<<<(NTOK * 64) / 256, 256>>>(pos);

    convert_hilo<<<(nBig + 255) / 256, 256>>>(hs, Ahi, Alo, nBig);
    convert_hilo<<<(nBig + 255) / 256, 256>>>(Wq, Bhi, Blo, nBig);
    hmma_gemm<QDIM><<<dim3(QDIM/128, NTOK/128), 256, 2*BUF_B>>>(Ahi, Alo, Bhi, Blo, Qb);
    convert_hilo<<<(nKV + 255) / 256, 256>>>(Wk, Bhi, Blo, nKV);
    hmma_gemm<KVDIM><<<dim3(KVDIM/128, NTOK/128), 256, 2*BUF_B>>>(Ahi, Alo, Bhi, Blo, Kb);
    convert_hilo<<<(nKV + 255) / 256, 256>>>(Wv, Bhi, Blo, nKV);
    hmma_gemm<KVDIM><<<dim3(KVDIM/128, NTOK/128), 256, 2*BUF_B>>>(Ahi, Alo, Bhi, Blo, Vb);

    rope_apply_kernel<<<dim3(NTOK, (HH + HKVV) / 4), 128>>>(Qb, Kb);

    flash_kernel<<<dim3(SS / 64, HH, BB), 128>>>(Qb, Kb, Vb, Ab);

    convert_hilo<<<(nBig + 255) / 256, 256>>>(Ab, Ahi, Alo, nBig);
    convert_hilo<<<(nBig + 255) / 256, 256>>>(Wo, Bhi, Blo, nBig);
    hmma_gemm<QDIM><<<dim3(QDIM/128, NTOK/128), 256, 2*BUF_B>>>(Ahi, Alo, Bhi, Blo, out);
}

// round 5
// speedup vs baseline: 2.2880x; 2.2687x over previous
#include <cuda_runtime.h>
#include <cuda_bf16.h>
#include <math.h>
#include <cstdint>

#define BB   2
#define SS   2048
#define DMM  4096
#define HH   32
#define HKVV 8
#define DD   128
#define NTOK (BB*SS)      // 4096
#define QDIM (HH*DD)      // 4096
#define KVDIM (HKVV*DD)   // 1024

// ---------------- scratch (__device__ globals; allocation-free rule) -------
__device__ __align__(256) float g_Q[(size_t)NTOK*QDIM];
__device__ __align__(256) float g_K[(size_t)NTOK*KVDIM];
__device__ __align__(256) float g_V[(size_t)NTOK*KVDIM];
__device__ __align__(256) float g_attn[(size_t)NTOK*QDIM];
__device__ float g_cos[(size_t)NTOK*64];
__device__ float g_sin[(size_t)NTOK*64];
__device__ __align__(256) __nv_bfloat16 g_Ahi[(size_t)NTOK*DMM];
__device__ __align__(256) __nv_bfloat16 g_Alo[(size_t)NTOK*DMM];
__device__ __align__(256) __nv_bfloat16 g_Bhi[(size_t)QDIM*DMM];
__device__ __align__(256) __nv_bfloat16 g_Blo[(size_t)QDIM*DMM];
// flash operands
__device__ __align__(256) __nv_bfloat16 g_Qhi[(size_t)NTOK*QDIM];
__device__ __align__(256) __nv_bfloat16 g_Qlo[(size_t)NTOK*QDIM];
__device__ __align__(256) __nv_bfloat16 g_Khi[(size_t)NTOK*KVDIM];
__device__ __align__(256) __nv_bfloat16 g_Klo[(size_t)NTOK*KVDIM];
__device__ __align__(256) __nv_bfloat16 g_Vth[(size_t)BB*HKVV*DD*SS];
__device__ __align__(256) __nv_bfloat16 g_Vtl[(size_t)BB*HKVV*DD*SS];

// ---------------------------- PTX helpers (baseline ISA only) --------------
__device__ __forceinline__ uint32_t smem_u32(const void* p) {
    uint32_t a;
    asm("{ .reg .u64 t; cvta.to.shared.u64 t, %1; cvt.u32.u64 %0, t; }"
        : "=r"(a) : "l"(p));
    return a;
}
#define CP_ASYNC16(saddr, gptr) \
    asm volatile("cp.async.cg.shared.global [%0], [%1], 16;\n" \
        :: "r"(saddr), "l"(gptr) : "memory")
#define CP_COMMIT() asm volatile("cp.async.commit_group;\n" ::: "memory")
#define CP_WAIT0()  asm volatile("cp.async.wait_group 0;\n" ::: "memory")

__device__ __forceinline__ void ldsm_x4(uint32_t* r, uint32_t addr) {
    asm volatile("ldmatrix.sync.aligned.m8n8.x4.shared.b16 {%0,%1,%2,%3}, [%4];\n"
        : "=r"(r[0]), "=r"(r[1]), "=r"(r[2]), "=r"(r[3]) : "r"(addr));
}
__device__ __forceinline__ void mma_bf16(float* d, const uint32_t* a,
                                         uint32_t b0, uint32_t b1) {
    asm volatile(
        "mma.sync.aligned.m16n8k16.row.col.f32.bf16.bf16.f32 "
        "{%0,%1,%2,%3}, {%4,%5,%6,%7}, {%8,%9}, {%0,%1,%2,%3};\n"
        : "+f"(d[0]), "+f"(d[1]), "+f"(d[2]), "+f"(d[3])
        : "r"(a[0]), "r"(a[1]), "r"(a[2]), "r"(a[3]), "r"(b0), "r"(b1));
}

// ---------------------------------------------------------------------------
// fp32 -> (bf16 hi, bf16 lo) split, with optional scale
// ---------------------------------------------------------------------------
__global__ void convert_hilo(const float* __restrict__ src,
                             __nv_bfloat16* __restrict__ hi,
                             __nv_bfloat16* __restrict__ lo, int n4, float scale)
{
    int i = blockIdx.x * blockDim.x + threadIdx.x;
    if (i >= n4) return;
    float4 x = ((const float4*)src)[i];
    x.x *= scale; x.y *= scale; x.z *= scale; x.w *= scale;
    __nv_bfloat16 h0 = __float2bfloat16(x.x);
    __nv_bfloat16 h1 = __float2bfloat16(x.y);
    __nv_bfloat16 h2 = __float2bfloat16(x.z);
    __nv_bfloat16 h3 = __float2bfloat16(x.w);
    __nv_bfloat16 l0 = __float2bfloat16(x.x - __bfloat162float(h0));
    __nv_bfloat16 l1 = __float2bfloat16(x.y - __bfloat162float(h1));
    __nv_bfloat16 l2 = __float2bfloat16(x.z - __bfloat162float(h2));
    __nv_bfloat16 l3 = __float2bfloat16(x.w - __bfloat162float(h3));
    __nv_bfloat162 hh0; hh0.x = h0; hh0.y = h1;
    __nv_bfloat162 hh1; hh1.x = h2; hh1.y = h3;
    __nv_bfloat162 ll0; ll0.x = l0; ll0.y = l1;
    __nv_bfloat162 ll1; ll1.x = l2; ll1.y = l3;
    ((__nv_bfloat162*)hi)[2*i]   = hh0;
    ((__nv_bfloat162*)hi)[2*i+1] = hh1;
    ((__nv_bfloat162*)lo)[2*i]   = ll0;
    ((__nv_bfloat162*)lo)[2*i+1] = ll1;
}

// V fp32 [t][kvh*128+d]  ->  Vt bf16 hi/lo [b][kvh][d][s]
__global__ void vtrans_hilo(const float* __restrict__ V,
                            __nv_bfloat16* __restrict__ th,
                            __nv_bfloat16* __restrict__ tl)
{
    int idx = blockIdx.x * blockDim.x + threadIdx.x;   // over rows*(SS/4)
    const int S4 = SS / 4;
    if (idx >= BB * HKVV * DD * S4) return;
    int s4  = idx % S4;
    int row = idx / S4;             // (b*HKVV + kvh)*128 + d
    int d   = row & 127;
    int kvh = (row >> 7) & (HKVV - 1);
    int b   = row >> 10;
    const float* src = V + ((size_t)(b * SS + s4 * 4)) * KVDIM + kvh * DD + d;
    __nv_bfloat16 h[4], l[4];
#pragma unroll
    for (int u = 0; u < 4; u++) {
        float x = src[(size_t)u * KVDIM];
        h[u] = __float2bfloat16(x);
        l[u] = __float2bfloat16(x - __bfloat162float(h[u]));
    }
    __nv_bfloat162 hh0; hh0.x = h[0]; hh0.y = h[1];
    __nv_bfloat162 hh1; hh1.x = h[2]; hh1.y = h[3];
    __nv_bfloat162 ll0; ll0.x = l[0]; ll0.y = l[1];
    __nv_bfloat162 ll1; ll1.x = l[2]; ll1.y = l[3];
    size_t o = (size_t)row * SS + s4 * 4;
    *(__nv_bfloat162*)(th + o)     = hh0;
    *(__nv_bfloat162*)(th + o + 2) = hh1;
    *(__nv_bfloat162*)(tl + o)     = ll0;
    *(__nv_bfloat162*)(tl + o + 2) = ll1;
}

// ---------------------------------------------------------------------------
// HMMA compensated-bf16 GEMM (unchanged from R4 passing version)
// ---------------------------------------------------------------------------
#define RSB   80
#define AHI_O 0
#define ALO_O 10240
#define BHI_O 20480
#define BLO_O 30720
#define BUF_B 40960

__device__ __forceinline__ void issue_loads(uint32_t sbuf,
    const __nv_bfloat16* __restrict__ Ahi, const __nv_bfloat16* __restrict__ Alo,
    const __nv_bfloat16* __restrict__ Bhi, const __nv_bfloat16* __restrict__ Blo,
    int bm, int bn, int kc, int tid)
{
    const size_t koff = (size_t)kc * 32;
#pragma unroll
    for (int i = 0; i < 2; i++) {
        int u = tid + i * 256;
        int row = u >> 2, c = u & 3;
        uint32_t so = row * RSB + c * 16;
        size_t ga = (size_t)(bm + row) * DMM + koff + c * 8;
        size_t gb = (size_t)(bn + row) * DMM + koff + c * 8;
        CP_ASYNC16(sbuf + AHI_O + so, Ahi + ga);
        CP_ASYNC16(sbuf + ALO_O + so, Alo + ga);
        CP_ASYNC16(sbuf + BHI_O + so, Bhi + gb);
        CP_ASYNC16(sbuf + BLO_O + so, Blo + gb);
    }
    CP_COMMIT();
}

template<int OUTD>
__global__ __launch_bounds__(256) void hmma_gemm(
    const __nv_bfloat16* __restrict__ Ahi, const __nv_bfloat16* __restrict__ Alo,
    const __nv_bfloat16* __restrict__ Bhi, const __nv_bfloat16* __restrict__ Blo,
    float* __restrict__ C)
{
    extern __shared__ __align__(128) char smc[];
    const int tid  = threadIdx.x;
    const int wid  = tid >> 5;
    const int lane = tid & 31;
    const int warp_m = wid >> 2;
    const int warp_n = wid & 3;
    const int bm = blockIdx.y * 128;
    const int bn = blockIdx.x * 128;

    const uint32_t sm0 = smem_u32(smc);

    float acc[4][4][4];
#pragma unroll
    for (int fm = 0; fm < 4; fm++)
#pragma unroll
        for (int fn = 0; fn < 4; fn++)
#pragma unroll
            for (int e = 0; e < 4; e++) acc[fm][fn][e] = 0.f;

    const uint32_t aoff = (uint32_t)((lane & 15) * RSB + (lane >> 4) * 16);
    const uint32_t boff = (uint32_t)(((lane & 7) + ((lane & 16) >> 1)) * RSB
                                     + ((lane & 8) ? 16 : 0));

    issue_loads(sm0, Ahi, Alo, Bhi, Blo, bm, bn, 0, tid);
    CP_WAIT0();
    __syncthreads();

    const int KT = DMM / 32;
    for (int kc = 0; kc < KT; kc++) {
        if (kc + 1 < KT)
            issue_loads(sm0 + ((kc + 1) & 1) * BUF_B, Ahi, Alo, Bhi, Blo, bm, bn, kc + 1, tid);

        const uint32_t sb = sm0 + (kc & 1) * BUF_B;
        const uint32_t abase = sb + (uint32_t)(warp_m * 64) * RSB;
        const uint32_t bbase = sb + (uint32_t)(warp_n * 32) * RSB;

#pragma unroll
        for (int ks = 0; ks < 2; ks++) {
            const uint32_t k0b = ks * 32;
            uint32_t Ah[4][4], Al[4][4], Bh[2][4], Bl[2][4];
#pragma unroll
            for (int fm = 0; fm < 4; fm++) {
                uint32_t ra = abase + (uint32_t)(fm * 16) * RSB + aoff + k0b;
                ldsm_x4(Ah[fm], ra + AHI_O);
                ldsm_x4(Al[fm], ra + ALO_O);
            }
#pragma unroll
            for (int g = 0; g < 2; g++) {
                uint32_t rb = bbase + (uint32_t)(g * 16) * RSB + boff + k0b;
                ldsm_x4(Bh[g], rb + BHI_O);
                ldsm_x4(Bl[g], rb + BLO_O);
            }
#pragma unroll
            for (int fm = 0; fm < 4; fm++)
#pragma unroll
                for (int fn = 0; fn < 4; fn++) {
                    const int g = fn >> 1, h = (fn & 1) * 2;
                    mma_bf16(acc[fm][fn], Ah[fm], Bh[g][h], Bh[g][h+1]);
                    mma_bf16(acc[fm][fn], Ah[fm], Bl[g][h], Bl[g][h+1]);
                    mma_bf16(acc[fm][fn], Al[fm], Bh[g][h], Bh[g][h+1]);
                }
        }
        CP_WAIT0();
        __syncthreads();
    }

    const int r0 = bm + warp_m * 64 + (lane >> 2);
    const int c0 = bn + warp_n * 32 + (lane & 3) * 2;
#pragma unroll
    for (int fm = 0; fm < 4; fm++)
#pragma unroll
        for (int fn = 0; fn < 4; fn++) {
            const int row = r0 + fm * 16;
            const int col = c0 + fn * 8;
            float2 v0 = make_float2(acc[fm][fn][0], acc[fm][fn][1]);
            float2 v1 = make_float2(acc[fm][fn][2], acc[fm][fn][3]);
            *(float2*)&C[(size_t)row * OUTD + col] = v0;
            *(float2*)&C[(size_t)(row + 8) * OUTD + col] = v1;
        }
}

// ---------------------------------------------------------------------------
// RoPE
// ---------------------------------------------------------------------------
__global__ void rope_table_kernel(const int* __restrict__ pos)
{
    int idx = blockIdx.x * blockDim.x + threadIdx.x;
    if (idx >= NTOK * 64) return;
    int t = idx >> 6;
    int i = idx & 63;
    double invf_d = exp(-((double)i / 64.0) * log(10000.0));
    float invf = (float)invf_d;
    float ang = (float)pos[t] * invf;
    double a = (double)ang;
    g_cos[idx] = (float)cos(a);
    g_sin[idx] = (float)sin(a);
}

__global__ void rope_apply_kernel(float* __restrict__ Q, float* __restrict__ K)
{
    int t    = blockIdx.x;
    int slot = blockIdx.y * 4 + (threadIdx.x >> 5);
    int lane = threadIdx.x & 31;
    float* base = (slot < HH)
        ? (Q + (size_t)t * QDIM + slot * DD)
        : (K + (size_t)t * KVDIM + (slot - HH) * DD);
#pragma unroll
    for (int rep = 0; rep < 2; rep++) {
        int i = lane + rep * 32;
        float c = g_cos[(size_t)t * 64 + i];
        float s = g_sin[(size_t)t * 64 + i];
        float x1 = base[i];
        float x2 = base[i + 64];
        base[i]      = x1 * c - x2 * s;
        base[i + 64] = x2 * c + x1 * s;
    }
}

// ---------------------------------------------------------------------------
// HMMA flash attention. BM=BN=64, D=128, 4 warps (warp owns m16 x N64 x D128).
// Q hi/lo frags register-resident (scale folded in). K hi/lo tiles [j][d],
// Vt hi/lo tiles [d][j] in smem via cp.async. Full 3-term compensation on
// both QK and PV. smem row strides: K 272B, Vt 144B (both mod 128 = 16 ->
// conflict-free ldmatrix).
// ---------------------------------------------------------------------------
#define KRS  272
#define VRS  144
#define SM_KH 0
#define SM_KL 17408
#define SM_VH 34816
#define SM_VL 53248
#define SM_FLASH_TOT 71680

__global__ __launch_bounds__(128) void flash_hmma(
    const __nv_bfloat16* __restrict__ Qh_g, const __nv_bfloat16* __restrict__ Ql_g,
    const __nv_bfloat16* __restrict__ Kh_g, const __nv_bfloat16* __restrict__ Kl_g,
    const __nv_bfloat16* __restrict__ Vh_g, const __nv_bfloat16* __restrict__ Vl_g,
    float* __restrict__ Og)
{
    extern __shared__ __align__(128) char smf[];
    const uint32_t s0 = smem_u32(smf);
    const int mt = blockIdx.x, h = blockIdx.y, b = blockIdx.z;
    const int kvh = h >> 2;
    const int tid = threadIdx.x, w = tid >> 5, lane = tid & 31;

    // ---- stage Q tile into K smem area, ldmatrix to registers -------------
    {
        const __nv_bfloat16* qh = Qh_g + ((size_t)(b * SS + mt * 64)) * QDIM + h * DD;
        const __nv_bfloat16* ql = Ql_g + ((size_t)(b * SS + mt * 64)) * QDIM + h * DD;
#pragma unroll
        for (int i = 0; i < 8; i++) {
            int u = tid + i * 128;
            int row = u >> 4, c = u & 15;
            size_t g = (size_t)row * QDIM + c * 8;
            uint32_t so = (uint32_t)(row * KRS + c * 16);
            CP_ASYNC16(s0 + SM_KH + so, qh + g);
            CP_ASYNC16(s0 + SM_KL + so, ql + g);
        }
        CP_COMMIT(); CP_WAIT0();
        __syncthreads();
    }
    const uint32_t aoff = (uint32_t)((lane & 15) * KRS + (lane >> 4) * 16);
    uint32_t Qh[8][4], Ql[8][4];
    {
        const uint32_t qb = s0 + (uint32_t)(w * 16) * KRS + aoff;
#pragma unroll
        for (int kk = 0; kk < 8; kk++) {
            ldsm_x4(Qh[kk], qb + SM_KH + 32 * kk);
            ldsm_x4(Ql[kk], qb + SM_KL + 32 * kk);
        }
    }
    __syncthreads();   // everyone done with Q staging area

    float O[16][4];
#pragma unroll
    for (int f = 0; f < 16; f++)
#pragma unroll
        for (int e = 0; e < 4; e++) O[f][e] = 0.f;
    float m0 = -1e30f, m1 = -1e30f, l0 = 0.f, l1 = 0.f;

    const __nv_bfloat16* khg = Kh_g + (size_t)(b * SS) * KVDIM + kvh * DD;
    const __nv_bfloat16* klg = Kl_g + (size_t)(b * SS) * KVDIM + kvh * DD;
    const __nv_bfloat16* vhg = Vh_g + ((size_t)(b * HKVV + kvh) * DD) * SS;
    const __nv_bfloat16* vlg = Vl_g + ((size_t)(b * HKVV + kvh) * DD) * SS;

    const uint32_t boffK = (uint32_t)(((lane & 7) + ((lane & 16) >> 1)) * KRS
                                      + ((lane & 8) ? 16 : 0));
    const uint32_t boffV = (uint32_t)(((lane & 7) + ((lane & 16) >> 1)) * VRS
                                      + ((lane & 8) ? 16 : 0));
    const int r_in0 = w * 16 + (lane >> 2);      // row within tile
    const int r_in1 = r_in0 + 8;

    for (int nt = 0; nt <= mt; nt++) {
        // ---- load K and Vt tiles ------------------------------------------
#pragma unroll
        for (int i = 0; i < 8; i++) {
            int u = tid + i * 128;
            int row = u >> 4, c = u & 15;
            size_t g = (size_t)(nt * 64 + row) * KVDIM + c * 8;
            uint32_t so = (uint32_t)(row * KRS + c * 16);
            CP_ASYNC16(s0 + SM_KH + so, khg + g);
            CP_ASYNC16(s0 + SM_KL + so, klg + g);
        }
#pragma unroll
        for (int i = 0; i < 8; i++) {
            int u = tid + i * 128;
            int row = u >> 3, c = u & 7;
            size_t g = (size_t)row * SS + nt * 64 + c * 8;
            uint32_t so = (uint32_t)(row * VRS + c * 16);
            CP_ASYNC16(s0 + SM_VH + so, vhg + g);
            CP_ASYNC16(s0 + SM_VL + so, vlg + g);
        }
        CP_COMMIT(); CP_WAIT0();
        __syncthreads();

        // ---- S = Q K^T (compensated) --------------------------------------
        float S[8][4];
#pragma unroll
        for (int f = 0; f < 8; f++)
#pragma unroll
            for (int e = 0; e < 4; e++) S[f][e] = 0.f;

#pragma unroll
        for (int kk = 0; kk < 8; kk++) {
            uint32_t KFh[4][4], KFl[4][4];
#pragma unroll
            for (int ng = 0; ng < 4; ng++) {
                uint32_t rb = s0 + (uint32_t)(ng * 16) * KRS + boffK + 32 * kk;
                ldsm_x4(KFh[ng], rb + SM_KH);
                ldsm_x4(KFl[ng], rb + SM_KL);
            }
#pragma unroll
            for (int ng = 0; ng < 4; ng++)
#pragma unroll
                for (int hh = 0; hh < 2; hh++) {
                    const int f = ng * 2 + hh;
                    mma_bf16(S[f], Qh[kk], KFh[ng][hh*2], KFh[ng][hh*2+1]);
                    mma_bf16(S[f], Qh[kk], KFl[ng][hh*2], KFl[ng][hh*2+1]);
                    mma_bf16(S[f], Ql[kk], KFh[ng][hh*2], KFh[ng][hh*2+1]);
                }
        }

        // ---- causal mask on diagonal tile ---------------------------------
        if (nt == mt) {
#pragma unroll
            for (int f = 0; f < 8; f++) {
                int n0 = f * 8 + (lane & 3) * 2;
                if (n0     > r_in0) S[f][0] = -1e30f;
                if (n0 + 1 > r_in0) S[f][1] = -1e30f;
                if (n0     > r_in1) S[f][2] = -1e30f;
                if (n0 + 1 > r_in1) S[f][3] = -1e30f;
            }
        }

        // ---- online softmax ------------------------------------------------
        float mx0 = -1e30f, mx1 = -1e30f;
#pragma unroll
        for (int f = 0; f < 8; f++) {
            mx0 = fmaxf(mx0, fmaxf(S[f][0], S[f][1]));
            mx1 = fmaxf(mx1, fmaxf(S[f][2], S[f][3]));
        }
        mx0 = fmaxf(mx0, __shfl_xor_sync(0xffffffffu, mx0, 1));
        mx0 = fmaxf(mx0, __shfl_xor_sync(0xffffffffu, mx0, 2));
        mx1 = fmaxf(mx1, __shfl_xor_sync(0xffffffffu, mx1, 1));
        mx1 = fmaxf(mx1, __shfl_xor_sync(0xffffffffu, mx1, 2));
        float mn0 = fmaxf(m0, mx0), mn1 = fmaxf(m1, mx1);
        float a0 = __expf(m0 - mn0), a1 = __expf(m1 - mn1);
        float sr0 = 0.f, sr1 = 0.f;
#pragma unroll
        for (int f = 0; f < 8; f++) {
            S[f][0] = __expf(S[f][0] - mn0);
            S[f][1] = __expf(S[f][1] - mn0);
            S[f][2] = __expf(S[f][2] - mn1);
            S[f][3] = __expf(S[f][3] - mn1);
            sr0 += S[f][0] + S[f][1];
            sr1 += S[f][2] + S[f][3];
        }
        sr0 += __shfl_xor_sync(0xffffffffu, sr0, 1);
        sr0 += __shfl_xor_sync(0xffffffffu, sr0, 2);
        sr1 += __shfl_xor_sync(0xffffffffu, sr1, 1);
        sr1 += __shfl_xor_sync(0xffffffffu, sr1, 2);
        l0 = l0 * a0 + sr0;
        l1 = l1 * a1 + sr1;
        m0 = mn0; m1 = mn1;
#pragma unroll
        for (int f = 0; f < 16; f++) {
            O[f][0] *= a0; O[f][1] *= a0;
            O[f][2] *= a1; O[f][3] *= a1;
        }

        // ---- P -> bf16 hi/lo A-frags --------------------------------------
        uint32_t Ph[4][4], Pl[4][4];
#pragma unroll
        for (int ks = 0; ks < 4; ks++) {
            const float* f0 = S[2*ks];
            const float* f1 = S[2*ks + 1];
#pragma unroll
            for (int q = 0; q < 4; q++) {
                float x = (q < 2) ? f0[(q & 1) * 2]     : f1[(q & 1) * 2];
                float y = (q < 2) ? f0[(q & 1) * 2 + 1] : f1[(q & 1) * 2 + 1];
                __nv_bfloat16 hx = __float2bfloat16(x);
                __nv_bfloat16 hy = __float2bfloat16(y);
                __nv_bfloat16 lx = __float2bfloat16(x - __bfloat162float(hx));
                __nv_bfloat16 ly = __float2bfloat16(y - __bfloat162float(hy));
                __nv_bfloat162 th; th.x = hx; th.y = hy;
                __nv_bfloat162 tl; tl.x = lx; tl.y = ly;
                Ph[ks][q] = *(uint32_t*)&th;
                Pl[ks][q] = *(uint32_t*)&tl;
            }
        }

        // ---- O += P Vt (compensated) --------------------------------------
#pragma unroll
        for (int ks = 0; ks < 4; ks++) {
#pragma unroll
            for (int g = 0; g < 8; g++) {
                uint32_t VFh[4], VFl[4];
                uint32_t rb = s0 + (uint32_t)(g * 16) * VRS + boffV + 32 * ks;
                ldsm_x4(VFh, rb + SM_VH);
                ldsm_x4(VFl, rb + SM_VL);
#pragma unroll
                for (int hh = 0; hh < 2; hh++) {
                    const int f = g * 2 + hh;
                    mma_bf16(O[f], Ph[ks], VFh[hh*2], VFh[hh*2+1]);
                    mma_bf16(O[f], Ph[ks], VFl[hh*2], VFl[hh*2+1]);
                    mma_bf16(O[f], Pl[ks], VFh[hh*2], VFh[hh*2+1]);
                }
            }
        }
        __syncthreads();   // before next tile overwrites smem
    }

    // ---- epilogue ----------------------------------------------------------
    float inv0 = 1.f / l0, inv1 = 1.f / l1;
    const int r0g = mt * 64 + r_in0;
    const int r1g = mt * 64 + r_in1;
#pragma unroll
    for (int f = 0; f < 16; f++) {
        const int col = h * DD + f * 8 + (lane & 3) * 2;
        float2 v0 = make_float2(O[f][0] * inv0, O[f][1] * inv0);
        float2 v1 = make_float2(O[f][2] * inv1, O[f][3] * inv1);
        *(float2*)&Og[(size_t)(b * SS + r0g) * QDIM + col] = v0;
        *(float2*)&Og[(size_t)(b * SS + r1g) * QDIM + col] = v1;
    }
}

// ---------------------------------------------------------------------------
extern "C" void kernel_launch(void* const* d_in, const int* in_sizes, int n_in,
                              void* d_out, int out_size)
{
    const float* hs  = (const float*)d_in[0];
    const int*   pos = (const int*)d_in[1];
    const float* Wq  = (const float*)d_in[2];
    const float* Wk  = (const float*)d_in[3];
    const float* Wv  = (const float*)d_in[4];
    const float* Wo  = (const float*)d_in[5];
    float* out = (float*)d_out;

    float *Qb, *Kb, *Vb, *Ab;
    __nv_bfloat16 *Ahi, *Alo, *Bhi, *Blo;
    __nv_bfloat16 *Qhi, *Qlo, *Khi, *Klo, *Vth, *Vtl;
    cudaGetSymbolAddress((void**)&Qb, g_Q);
    cudaGetSymbolAddress((void**)&Kb, g_K);
    cudaGetSymbolAddress((void**)&Vb, g_V);
    cudaGetSymbolAddress((void**)&Ab, g_attn);
    cudaGetSymbolAddress((void**)&Ahi, g_Ahi);
    cudaGetSymbolAddress((void**)&Alo, g_Alo);
    cudaGetSymbolAddress((void**)&Bhi, g_Bhi);
    cudaGetSymbolAddress((void**)&Blo, g_Blo);
    cudaGetSymbolAddress((void**)&Qhi, g_Qhi);
    cudaGetSymbolAddress((void**)&Qlo, g_Qlo);
    cudaGetSymbolAddress((void**)&Khi, g_Khi);
    cudaGetSymbolAddress((void**)&Klo, g_Klo);
    cudaGetSymbolAddress((void**)&Vth, g_Vth);
    cudaGetSymbolAddress((void**)&Vtl, g_Vtl);

    cudaFuncSetAttribute(hmma_gemm<QDIM>,  cudaFuncAttributeMaxDynamicSharedMemorySize, 2*BUF_B);
    cudaFuncSetAttribute(hmma_gemm<KVDIM>, cudaFuncAttributeMaxDynamicSharedMemorySize, 2*BUF_B);
    cudaFuncSetAttribute(flash_hmma, cudaFuncAttributeMaxDynamicSharedMemorySize, SM_FLASH_TOT);

    const int nBig = NTOK * DMM / 4;
    const int nKV  = KVDIM * DMM / 4;
    const float qscale = 0.08838834764831843f;   // 1/sqrt(128)

    rope_table_kernel<<<(NTOK * 64) / 256, 256>>>(pos);

    convert_hilo<<<(nBig + 255) / 256, 256>>>(hs, Ahi, Alo, nBig, 1.f);
    convert_hilo<<<(nBig + 255) / 256, 256>>>(Wq, Bhi, Blo, nBig, 1.f);
    hmma_gemm<QDIM><<<dim3(QDIM/128, NTOK/128), 256, 2*BUF_B>>>(Ahi, Alo, Bhi, Blo, Qb);
    convert_hilo<<<(nKV + 255) / 256, 256>>>(Wk, Bhi, Blo, nKV, 1.f);
    hmma_gemm<KVDIM><<<dim3(KVDIM/128, NTOK/128), 256, 2*BUF_B>>>(Ahi, Alo, Bhi, Blo, Kb);
    convert_hilo<<<(nKV + 255) / 256, 256>>>(Wv, Bhi, Blo, nKV, 1.f);
    hmma_gemm<KVDIM><<<dim3(KVDIM/128, NTOK/128), 256, 2*BUF_B>>>(Ahi, Alo, Bhi, Blo, Vb);

    rope_apply_kernel<<<dim3(NTOK, (HH + HKVV) / 4), 128>>>(Qb, Kb);

    // flash operand conversions
    const int nQ  = NTOK * QDIM / 4;
    const int nK  = NTOK * KVDIM / 4;
    convert_hilo<<<(nQ + 255) / 256, 256>>>(Qb, Qhi, Qlo, nQ, qscale);
    convert_hilo<<<(nK + 255) / 256, 256>>>(Kb, Khi, Klo, nK, 1.f);
    {
        int nV = BB * HKVV * DD * (SS / 4);
        vtrans_hilo<<<(nV + 255) / 256, 256>>>(Vb, Vth, Vtl);
    }

    flash_hmma<<<dim3(SS / 64, HH, BB), 128, SM_FLASH_TOT>>>(
        Qhi, Qlo, Khi, Klo, Vth, Vtl, Ab);

    convert_hilo<<<(nBig + 255) / 256, 256>>>(Ab, Ahi, Alo, nBig, 1.f);
    convert_hilo<<<(nBig + 255) / 256, 256>>>(Wo, Bhi, Blo, nBig, 1.f);
    hmma_gemm<QDIM><<<dim3(QDIM/128, NTOK/128), 256, 2*BUF_B>>>(Ahi, Alo, Bhi, Blo, out);
}